// round 1
// baseline (speedup 1.0000x reference)
#include <cuda_runtime.h>

// Problem constants
#define BATCH   4
#define GRID_HW 512
#define HWO     (GRID_HW * GRID_HW)          // 262144 = 2^18
#define NPIX    (BATCH * HWO)                // 1048576 = 2^20
#define FEAT    16

// Level sizes (square textures)
#define W1 1024
#define W2 512
#define W3 256
#define W4 128

// Feature-interleaved packed textures: packed[(y*W + x)] holds 16 floats = 4 float4.
// Static __device__ scratch (allocation-free per harness rules). ~85 MB total.
__device__ __align__(16) static float4 g_p1[W1 * W1 * 4];   // 64 MB
__device__ __align__(16) static float4 g_p2[W2 * W2 * 4];   // 16 MB
__device__ __align__(16) static float4 g_p3[W3 * W3 * 4];   //  4 MB
__device__ __align__(16) static float4 g_p4[W4 * W4 * 4];   //  1 MB

// ---------------------------------------------------------------------------
// Repack: src (F, H, W) channel-major  ->  dst AoS: dst[lin*4 + f4] (16 floats
// per texel, contiguous). Pure 16 x HW transpose in linear index space.
// Each thread handles 4 consecutive linear texels, vectorized both directions.
// ---------------------------------------------------------------------------
__global__ void __launch_bounds__(256) repack_kernel(const float* __restrict__ src,
                                                     int HW, int level) {
    float4* dst = (level == 0) ? g_p1 : (level == 1) ? g_p2 : (level == 2) ? g_p3 : g_p4;

    int g = blockIdx.x * blockDim.x + threadIdx.x;   // group of 4 texels
    int lin = g * 4;
    if (lin >= HW) return;

    // Load: for each feature, 4 consecutive texels (coalesced LDG.128 across warp).
    float v[FEAT][4];
#pragma unroll
    for (int f = 0; f < FEAT; f++) {
        float4 t = __ldcs((const float4*)(src + (size_t)f * HW + lin));  // streaming read
        v[f][0] = t.x; v[f][1] = t.y; v[f][2] = t.z; v[f][3] = t.w;
    }
    // Store transposed: per texel j, 4 float4 covering 16 features (contiguous 64B).
#pragma unroll
    for (int j = 0; j < 4; j++) {
#pragma unroll
        for (int f4 = 0; f4 < 4; f4++) {
            float4 o;
            o.x = v[f4 * 4 + 0][j];
            o.y = v[f4 * 4 + 1][j];
            o.z = v[f4 * 4 + 2][j];
            o.w = v[f4 * 4 + 3][j];
            dst[(size_t)(lin + j) * 4 + f4] = o;
        }
    }
}

// ---------------------------------------------------------------------------
// Bilinear sample (padding_mode='border', align_corners=False) of one level
// for one feature-quad. One float4 gather per corner.
// ---------------------------------------------------------------------------
__device__ __forceinline__ void sample_level(const float4* __restrict__ tex, int W,
                                             float gx, float gy, int fq, float4& acc) {
    const float Wf = (float)W;
    float ix = ((gx + 1.0f) * Wf - 1.0f) * 0.5f;
    float iy = ((gy + 1.0f) * Wf - 1.0f) * 0.5f;
    ix = fminf(fmaxf(ix, 0.0f), Wf - 1.0f);
    iy = fminf(fmaxf(iy, 0.0f), Wf - 1.0f);
    float x0f = floorf(ix);
    float y0f = floorf(iy);
    float wx = ix - x0f;
    float wy = iy - y0f;
    int x0 = (int)x0f;
    int y0 = (int)y0f;
    int x1 = min(x0 + 1, W - 1);
    int y1 = min(y0 + 1, W - 1);
    int r0 = y0 * W;
    int r1 = y1 * W;

    float4 v00 = __ldg(tex + (size_t)(r0 + x0) * 4 + fq);
    float4 v01 = __ldg(tex + (size_t)(r0 + x1) * 4 + fq);
    float4 v10 = __ldg(tex + (size_t)(r1 + x0) * 4 + fq);
    float4 v11 = __ldg(tex + (size_t)(r1 + x1) * 4 + fq);

    float w00 = (1.0f - wx) * (1.0f - wy);
    float w01 = wx * (1.0f - wy);
    float w10 = (1.0f - wx) * wy;
    float w11 = wx * wy;

    acc.x += w00 * v00.x + w01 * v01.x + w10 * v10.x + w11 * v11.x;
    acc.y += w00 * v00.y + w01 * v01.y + w10 * v10.y + w11 * v11.y;
    acc.z += w00 * v00.z + w01 * v01.z + w10 * v10.z + w11 * v11.z;
    acc.w += w00 * v00.w + w01 * v01.w + w10 * v10.w + w11 * v11.w;
}

// ---------------------------------------------------------------------------
// Gather: one thread per (pixel, feature-quad). t = fq * 2^20 + p so that
// consecutive threads share fq and have consecutive pixels (coalesced grid
// loads and output stores).
// ---------------------------------------------------------------------------
__global__ void __launch_bounds__(256) gather_kernel(const float* __restrict__ grid,
                                                     float* __restrict__ out) {
    int t = blockIdx.x * blockDim.x + threadIdx.x;
    int fq = t >> 20;            // 0..3
    int p  = t & (NPIX - 1);     // 0..2^20-1

    float2 g = __ldg((const float2*)grid + p);

    float4 acc = make_float4(0.0f, 0.0f, 0.0f, 0.0f);
    sample_level(g_p1, W1, g.x, g.y, fq, acc);
    sample_level(g_p2, W2, g.x, g.y, fq, acc);
    sample_level(g_p3, W3, g.x, g.y, fq, acc);
    sample_level(g_p4, W4, g.x, g.y, fq, acc);

    int b  = p >> 18;            // batch
    int hw = p & (HWO - 1);
    // out layout: (B, F, Ho, Wo)
    size_t base = ((size_t)(b * FEAT + fq * 4) << 18) | (unsigned)hw;
    // Streaming stores: don't evict packed textures from L2.
    __stcs(out + base,            acc.x);
    __stcs(out + base + HWO,      acc.y);
    __stcs(out + base + 2 * HWO,  acc.z);
    __stcs(out + base + 3 * HWO,  acc.w);
}

extern "C" void kernel_launch(void* const* d_in, const int* in_sizes, int n_in,
                              void* d_out, int out_size) {
    const float* x    = (const float*)d_in[0];   // (4, 512, 512, 2)
    const float* tex1 = (const float*)d_in[1];   // (16, 1024, 1024)
    const float* tex2 = (const float*)d_in[2];   // (16, 512, 512)
    const float* tex3 = (const float*)d_in[3];   // (16, 256, 256)
    const float* tex4 = (const float*)d_in[4];   // (16, 128, 128)
    float* out = (float*)d_out;                  // (4, 16, 512, 512)

    // Repack each level to feature-interleaved AoS.
    repack_kernel<<<(W1 * W1 / 4 + 255) / 256, 256>>>(tex1, W1 * W1, 0);
    repack_kernel<<<(W2 * W2 / 4 + 255) / 256, 256>>>(tex2, W2 * W2, 1);
    repack_kernel<<<(W3 * W3 / 4 + 255) / 256, 256>>>(tex3, W3 * W3, 2);
    repack_kernel<<<(W4 * W4 / 4 + 255) / 256, 256>>>(tex4, W4 * W4, 3);

    // Gather + blend + sum levels.
    const int total = 4 * NPIX;                  // (pixel, feature-quad) threads
    gather_kernel<<<total / 256, 256>>>(x, out);
}

// round 2
// speedup vs baseline: 2.1631x; 2.1631x over previous
#include <cuda_runtime.h>

// Problem constants
#define BATCH   4
#define GRID_HW 512
#define HWO     (GRID_HW * GRID_HW)          // 262144 = 2^18
#define NPIX    (BATCH * HWO)                // 1048576 = 2^20
#define FEAT    16

// Level sizes (square textures)
#define W1 1024
#define W2 512
#define W3 256
#define W4 128

// Feature-interleaved packed textures: packed[(y*W + x)] holds 16 floats = 4 float4.
// Static __device__ scratch (allocation-free per harness rules). ~85 MB total.
__device__ __align__(16) static float4 g_p1[W1 * W1 * 4];   // 64 MB
__device__ __align__(16) static float4 g_p2[W2 * W2 * 4];   // 16 MB
__device__ __align__(16) static float4 g_p3[W3 * W3 * 4];   //  4 MB
__device__ __align__(16) static float4 g_p4[W4 * W4 * 4];   //  1 MB

// ---------------------------------------------------------------------------
// Repack: src (F, H, W) channel-major  ->  dst AoS: dst[lin*4 + f4] (16 floats
// per texel, contiguous 64B). Each thread handles 4 consecutive linear texels.
// ---------------------------------------------------------------------------
__global__ void __launch_bounds__(256) repack_kernel(const float* __restrict__ src,
                                                     int HW, int level) {
    float4* dst = (level == 0) ? g_p1 : (level == 1) ? g_p2 : (level == 2) ? g_p3 : g_p4;

    int g = blockIdx.x * blockDim.x + threadIdx.x;   // group of 4 texels
    int lin = g * 4;
    if (lin >= HW) return;

    float v[FEAT][4];
#pragma unroll
    for (int f = 0; f < FEAT; f++) {
        float4 t = __ldcs((const float4*)(src + (size_t)f * HW + lin));  // streaming read
        v[f][0] = t.x; v[f][1] = t.y; v[f][2] = t.z; v[f][3] = t.w;
    }
#pragma unroll
    for (int j = 0; j < 4; j++) {
#pragma unroll
        for (int f4 = 0; f4 < 4; f4++) {
            float4 o;
            o.x = v[f4 * 4 + 0][j];
            o.y = v[f4 * 4 + 1][j];
            o.z = v[f4 * 4 + 2][j];
            o.w = v[f4 * 4 + 3][j];
            dst[(size_t)(lin + j) * 4 + f4] = o;
        }
    }
}

// ---------------------------------------------------------------------------
// Bilinear sample (padding_mode='border', align_corners=False) of one level
// for one feature-quad. The 4 lanes of a pixel group (fq=0..3) access
// contiguous 16B slices of the same 64B texel record -> the L1 coalescer
// merges each corner into a single line access per group.
// ---------------------------------------------------------------------------
__device__ __forceinline__ void sample_level(const float4* __restrict__ tex, int W,
                                             float gx, float gy, int fq, float4& acc) {
    const float Wf = (float)W;
    float ix = ((gx + 1.0f) * Wf - 1.0f) * 0.5f;
    float iy = ((gy + 1.0f) * Wf - 1.0f) * 0.5f;
    ix = fminf(fmaxf(ix, 0.0f), Wf - 1.0f);
    iy = fminf(fmaxf(iy, 0.0f), Wf - 1.0f);
    float x0f = floorf(ix);
    float y0f = floorf(iy);
    float wx = ix - x0f;
    float wy = iy - y0f;
    int x0 = (int)x0f;
    int y0 = (int)y0f;
    int x1 = min(x0 + 1, W - 1);
    int y1 = min(y0 + 1, W - 1);
    int r0 = y0 * W;
    int r1 = y1 * W;

    float4 v00 = __ldg(tex + (size_t)(r0 + x0) * 4 + fq);
    float4 v01 = __ldg(tex + (size_t)(r0 + x1) * 4 + fq);
    float4 v10 = __ldg(tex + (size_t)(r1 + x0) * 4 + fq);
    float4 v11 = __ldg(tex + (size_t)(r1 + x1) * 4 + fq);

    float w00 = (1.0f - wx) * (1.0f - wy);
    float w01 = wx * (1.0f - wy);
    float w10 = (1.0f - wx) * wy;
    float w11 = wx * wy;

    acc.x += w00 * v00.x + w01 * v01.x + w10 * v10.x + w11 * v11.x;
    acc.y += w00 * v00.y + w01 * v01.y + w10 * v10.y + w11 * v11.y;
    acc.z += w00 * v00.z + w01 * v01.z + w10 * v10.z + w11 * v11.z;
    acc.w += w00 * v00.w + w01 * v01.w + w10 * v10.w + w11 * v11.w;
}

// ---------------------------------------------------------------------------
// Gather: one thread per (pixel, feature-quad). t = p*4 + fq so that each
// group of 4 consecutive lanes covers one pixel's 64B texel record -> gathers
// coalesce 4:1 inside the warp.
// ---------------------------------------------------------------------------
__global__ void __launch_bounds__(256) gather_kernel(const float* __restrict__ grid,
                                                     float* __restrict__ out) {
    int t = blockIdx.x * blockDim.x + threadIdx.x;
    int p  = t >> 2;             // pixel 0..2^20-1
    int fq = t & 3;              // feature quad 0..3

    float2 g = __ldg((const float2*)grid + p);   // 4 lanes broadcast same 8B

    float4 acc = make_float4(0.0f, 0.0f, 0.0f, 0.0f);
    sample_level(g_p1, W1, g.x, g.y, fq, acc);
    sample_level(g_p2, W2, g.x, g.y, fq, acc);
    sample_level(g_p3, W3, g.x, g.y, fq, acc);
    sample_level(g_p4, W4, g.x, g.y, fq, acc);

    int b  = p >> 18;            // batch
    int hw = p & (HWO - 1);
    // out layout: (B, F, Ho, Wo)
    size_t base = ((size_t)(b * FEAT + fq * 4) << 18) | (unsigned)hw;
    // Streaming stores: don't evict packed textures from L2.
    __stcs(out + base,            acc.x);
    __stcs(out + base + HWO,      acc.y);
    __stcs(out + base + 2 * HWO,  acc.z);
    __stcs(out + base + 3 * HWO,  acc.w);
}

extern "C" void kernel_launch(void* const* d_in, const int* in_sizes, int n_in,
                              void* d_out, int out_size) {
    const float* x    = (const float*)d_in[0];   // (4, 512, 512, 2)
    const float* tex1 = (const float*)d_in[1];   // (16, 1024, 1024)
    const float* tex2 = (const float*)d_in[2];   // (16, 512, 512)
    const float* tex3 = (const float*)d_in[3];   // (16, 256, 256)
    const float* tex4 = (const float*)d_in[4];   // (16, 128, 128)
    float* out = (float*)d_out;                  // (4, 16, 512, 512)

    // Repack each level to feature-interleaved AoS.
    repack_kernel<<<(W1 * W1 / 4 + 255) / 256, 256>>>(tex1, W1 * W1, 0);
    repack_kernel<<<(W2 * W2 / 4 + 255) / 256, 256>>>(tex2, W2 * W2, 1);
    repack_kernel<<<(W3 * W3 / 4 + 255) / 256, 256>>>(tex3, W3 * W3, 2);
    repack_kernel<<<(W4 * W4 / 4 + 255) / 256, 256>>>(tex4, W4 * W4, 3);

    // Gather + blend + sum levels. One thread per (pixel, feature-quad).
    const int total = 4 * NPIX;
    gather_kernel<<<total / 256, 256>>>(x, out);
}

// round 3
// speedup vs baseline: 3.1391x; 1.4512x over previous
#include <cuda_runtime.h>
#include <cuda_fp16.h>

// Problem constants
#define GRID_HW 512
#define HWO     (GRID_HW * GRID_HW)          // 262144 = 2^18
#define NPIX    (4 * HWO)                    // 1048576 = 2^20
#define FEAT    16

// Level sizes (square textures)
#define W1 1024
#define W2 512
#define W3 256
#define W4 128
#define N1 (W1 * W1)
#define N2 (W2 * W2)
#define N3 (W3 * W3)
#define N4 (W4 * W4)

// Feature-interleaved fp16 packed textures: one texel = 16 halfs = 32B record.
// Static __device__ scratch (allocation-free). 42.5 MB total -> L2 resident.
__device__ __align__(16) static uint4 g_p1[N1 * 2];   // 32 MB
__device__ __align__(16) static uint4 g_p2[N2 * 2];   //  8 MB
__device__ __align__(16) static uint4 g_p3[N3 * 2];   //  2 MB
__device__ __align__(16) static uint4 g_p4[N4 * 2];   //  0.5 MB

// ---------------------------------------------------------------------------
// Fused repack: all 4 levels in one kernel. src (F, H, W) fp32 channel-major
// -> dst AoS fp16: 16 halfs per texel, contiguous 32B. One texel per thread:
// loads are coalesced LDG.32 per feature; the two STG.128 per thread have
// lanes striding 32B, so each 128B line is covered by 4 lanes (no replays).
// ---------------------------------------------------------------------------
__global__ void __launch_bounds__(256) repack_fused_kernel(
    const float* __restrict__ t1, const float* __restrict__ t2,
    const float* __restrict__ t3, const float* __restrict__ t4) {
    int idx = blockIdx.x * blockDim.x + threadIdx.x;

    const float* src;
    uint4* dst;
    int lin, HW;
    if (idx < N1)                { src = t1; dst = g_p1; lin = idx;                HW = N1; }
    else if (idx < N1 + N2)      { src = t2; dst = g_p2; lin = idx - N1;           HW = N2; }
    else if (idx < N1 + N2 + N3) { src = t3; dst = g_p3; lin = idx - N1 - N2;      HW = N3; }
    else if (idx < N1 + N2 + N3 + N4) { src = t4; dst = g_p4; lin = idx - N1 - N2 - N3; HW = N4; }
    else return;

    half2 h[8];
#pragma unroll
    for (int f = 0; f < 8; f++) {
        float a = __ldcs(src + (size_t)(2 * f) * HW + lin);
        float b = __ldcs(src + (size_t)(2 * f + 1) * HW + lin);
        h[f] = __floats2half2_rn(a, b);
    }
    uint4 lo, hi;
    lo.x = *reinterpret_cast<unsigned*>(&h[0]);
    lo.y = *reinterpret_cast<unsigned*>(&h[1]);
    lo.z = *reinterpret_cast<unsigned*>(&h[2]);
    lo.w = *reinterpret_cast<unsigned*>(&h[3]);
    hi.x = *reinterpret_cast<unsigned*>(&h[4]);
    hi.y = *reinterpret_cast<unsigned*>(&h[5]);
    hi.z = *reinterpret_cast<unsigned*>(&h[6]);
    hi.w = *reinterpret_cast<unsigned*>(&h[7]);
    dst[(size_t)lin * 2 + 0] = lo;
    dst[(size_t)lin * 2 + 1] = hi;
}

// Unpack 4 packed halfs (one uint2 = 8B) to float4.
__device__ __forceinline__ float4 up4(uint2 u) {
    half2 a = *reinterpret_cast<half2*>(&u.x);
    half2 b = *reinterpret_cast<half2*>(&u.y);
    float2 fa = __half22float2(a);
    float2 fb = __half22float2(b);
    return make_float4(fa.x, fa.y, fb.x, fb.y);
}

// ---------------------------------------------------------------------------
// Bilinear sample (padding_mode='border', align_corners=False) of one fp16
// packed level for one feature-quad. 4 lanes of a pixel group read contiguous
// 8B slices of the 32B texel record -> one 32B sector per corner per pixel.
// Interpolation weights and blending stay fp32.
// ---------------------------------------------------------------------------
__device__ __forceinline__ void sample_level(const uint2* __restrict__ tex, int W,
                                             float gx, float gy, int fq, float4& acc) {
    const float Wf = (float)W;
    float ix = ((gx + 1.0f) * Wf - 1.0f) * 0.5f;
    float iy = ((gy + 1.0f) * Wf - 1.0f) * 0.5f;
    ix = fminf(fmaxf(ix, 0.0f), Wf - 1.0f);
    iy = fminf(fmaxf(iy, 0.0f), Wf - 1.0f);
    float x0f = floorf(ix);
    float y0f = floorf(iy);
    float wx = ix - x0f;
    float wy = iy - y0f;
    int x0 = (int)x0f;
    int y0 = (int)y0f;
    int x1 = min(x0 + 1, W - 1);
    int y1 = min(y0 + 1, W - 1);
    int r0 = y0 * W;
    int r1 = y1 * W;

    // texel record = 4 uint2; lane owns slice fq
    uint2 u00 = __ldg(tex + ((size_t)(r0 + x0) * 4 + fq));
    uint2 u01 = __ldg(tex + ((size_t)(r0 + x1) * 4 + fq));
    uint2 u10 = __ldg(tex + ((size_t)(r1 + x0) * 4 + fq));
    uint2 u11 = __ldg(tex + ((size_t)(r1 + x1) * 4 + fq));

    float4 v00 = up4(u00);
    float4 v01 = up4(u01);
    float4 v10 = up4(u10);
    float4 v11 = up4(u11);

    float w00 = (1.0f - wx) * (1.0f - wy);
    float w01 = wx * (1.0f - wy);
    float w10 = (1.0f - wx) * wy;
    float w11 = wx * wy;

    acc.x += w00 * v00.x + w01 * v01.x + w10 * v10.x + w11 * v11.x;
    acc.y += w00 * v00.y + w01 * v01.y + w10 * v10.y + w11 * v11.y;
    acc.z += w00 * v00.z + w01 * v01.z + w10 * v10.z + w11 * v11.z;
    acc.w += w00 * v00.w + w01 * v01.w + w10 * v10.w + w11 * v11.w;
}

// ---------------------------------------------------------------------------
// Gather: one thread per (pixel, feature-quad). t = p*4 + fq so each group of
// 4 consecutive lanes covers one pixel's 32B texel record.
// ---------------------------------------------------------------------------
__global__ void __launch_bounds__(256) gather_kernel(const float* __restrict__ grid,
                                                     float* __restrict__ out) {
    int t = blockIdx.x * blockDim.x + threadIdx.x;
    int p  = t >> 2;             // pixel 0..2^20-1
    int fq = t & 3;              // feature quad 0..3

    float2 g = __ldg((const float2*)grid + p);   // 4 lanes broadcast same 8B

    float4 acc = make_float4(0.0f, 0.0f, 0.0f, 0.0f);
    sample_level((const uint2*)g_p1, W1, g.x, g.y, fq, acc);
    sample_level((const uint2*)g_p2, W2, g.x, g.y, fq, acc);
    sample_level((const uint2*)g_p3, W3, g.x, g.y, fq, acc);
    sample_level((const uint2*)g_p4, W4, g.x, g.y, fq, acc);

    int b  = p >> 18;            // batch
    int hw = p & (HWO - 1);
    // out layout: (B, F, Ho, Wo)
    size_t base = ((size_t)(b * FEAT + fq * 4) << 18) | (unsigned)hw;
    // Streaming stores: don't evict packed textures from L2.
    __stcs(out + base,            acc.x);
    __stcs(out + base + HWO,      acc.y);
    __stcs(out + base + 2 * HWO,  acc.z);
    __stcs(out + base + 3 * HWO,  acc.w);
}

extern "C" void kernel_launch(void* const* d_in, const int* in_sizes, int n_in,
                              void* d_out, int out_size) {
    const float* x    = (const float*)d_in[0];   // (4, 512, 512, 2)
    const float* tex1 = (const float*)d_in[1];   // (16, 1024, 1024)
    const float* tex2 = (const float*)d_in[2];   // (16, 512, 512)
    const float* tex3 = (const float*)d_in[3];   // (16, 256, 256)
    const float* tex4 = (const float*)d_in[4];   // (16, 128, 128)
    float* out = (float*)d_out;                  // (4, 16, 512, 512)

    // Fused repack: all levels -> fp16 AoS records.
    const int total_texels = N1 + N2 + N3 + N4;  // 1,376,256
    repack_fused_kernel<<<(total_texels + 255) / 256, 256>>>(tex1, tex2, tex3, tex4);

    // Gather + blend + sum levels. One thread per (pixel, feature-quad).
    gather_kernel<<<(4 * NPIX) / 256, 256>>>(x, out);
}

// round 5
// speedup vs baseline: 3.1648x; 1.0082x over previous
#include <cuda_runtime.h>
#include <cuda_fp16.h>

// Problem constants
#define GRID_HW 512
#define HWO     (GRID_HW * GRID_HW)          // 262144 = 2^18
#define NPIX    (4 * HWO)                    // 1048576 = 2^20
#define FEAT    16

// Level sizes (square textures)
#define W1 1024
#define W2 512
#define W3 256
#define W4 128
#define N1 (W1 * W1)
#define N2 (W2 * W2)
#define N3 (W3 * W3)
#define N4 (W4 * W4)

// Feature-interleaved fp16 packed textures: one texel = 16 halfs = 32B record
// stored as 2 x uint4 (features 0-7, 8-15). 42.5 MB total -> L2 resident.
__device__ __align__(16) static uint4 g_p1[N1 * 2];   // 32 MB
__device__ __align__(16) static uint4 g_p2[N2 * 2];   //  8 MB
__device__ __align__(16) static uint4 g_p3[N3 * 2];   //  2 MB
__device__ __align__(16) static uint4 g_p4[N4 * 2];   //  0.5 MB

// ---------------------------------------------------------------------------
// Fused repack: all 4 levels in one kernel. src (F, H, W) fp32 channel-major
// -> dst AoS fp16 records. One texel per thread; per-feature loads coalesce
// across the warp; the two STG.128 cover contiguous 512B per warp.
// ---------------------------------------------------------------------------
__global__ void __launch_bounds__(256) repack_fused_kernel(
    const float* __restrict__ t1, const float* __restrict__ t2,
    const float* __restrict__ t3, const float* __restrict__ t4) {
    int idx = blockIdx.x * blockDim.x + threadIdx.x;

    const float* src;
    uint4* dst;
    int lin, HW;
    if (idx < N1)                { src = t1; dst = g_p1; lin = idx;                HW = N1; }
    else if (idx < N1 + N2)      { src = t2; dst = g_p2; lin = idx - N1;           HW = N2; }
    else if (idx < N1 + N2 + N3) { src = t3; dst = g_p3; lin = idx - N1 - N2;      HW = N3; }
    else if (idx < N1 + N2 + N3 + N4) { src = t4; dst = g_p4; lin = idx - N1 - N2 - N3; HW = N4; }
    else return;

    half2 h[8];
#pragma unroll
    for (int f = 0; f < 8; f++) {
        float a = __ldcs(src + (size_t)(2 * f) * HW + lin);
        float b = __ldcs(src + (size_t)(2 * f + 1) * HW + lin);
        h[f] = __floats2half2_rn(a, b);
    }
    uint4 lo, hi;
    lo.x = *reinterpret_cast<unsigned*>(&h[0]);
    lo.y = *reinterpret_cast<unsigned*>(&h[1]);
    lo.z = *reinterpret_cast<unsigned*>(&h[2]);
    lo.w = *reinterpret_cast<unsigned*>(&h[3]);
    hi.x = *reinterpret_cast<unsigned*>(&h[4]);
    hi.y = *reinterpret_cast<unsigned*>(&h[5]);
    hi.z = *reinterpret_cast<unsigned*>(&h[6]);
    hi.w = *reinterpret_cast<unsigned*>(&h[7]);
    dst[(size_t)lin * 2 + 0] = lo;
    dst[(size_t)lin * 2 + 1] = hi;
}

// Unpack 8 packed halfs (one uint4 = 16B) into 8 floats.
__device__ __forceinline__ void up8(uint4 u, float* v) {
    float2 f0 = __half22float2(*reinterpret_cast<half2*>(&u.x));
    float2 f1 = __half22float2(*reinterpret_cast<half2*>(&u.y));
    float2 f2 = __half22float2(*reinterpret_cast<half2*>(&u.z));
    float2 f3 = __half22float2(*reinterpret_cast<half2*>(&u.w));
    v[0] = f0.x; v[1] = f0.y; v[2] = f1.x; v[3] = f1.y;
    v[4] = f2.x; v[5] = f2.y; v[6] = f3.x; v[7] = f3.y;
}

// ---------------------------------------------------------------------------
// Bilinear sample (padding_mode='border', align_corners=False) of one fp16
// packed level for one feature-half (8 features). 2 lanes of a pixel pair
// read the two contiguous 16B halves of the 32B texel record -> one L1
// wavefront / one 32B L2 sector per corner per pixel. Blending stays fp32.
// ---------------------------------------------------------------------------
__device__ __forceinline__ void sample_level(const uint4* __restrict__ tex, int W,
                                             float gx, float gy, int h, float* acc) {
    const float Wf = (float)W;
    float ix = ((gx + 1.0f) * Wf - 1.0f) * 0.5f;
    float iy = ((gy + 1.0f) * Wf - 1.0f) * 0.5f;
    ix = fminf(fmaxf(ix, 0.0f), Wf - 1.0f);
    iy = fminf(fmaxf(iy, 0.0f), Wf - 1.0f);
    float x0f = floorf(ix);
    float y0f = floorf(iy);
    float wx = ix - x0f;
    float wy = iy - y0f;
    int x0 = (int)x0f;
    int y0 = (int)y0f;
    int x1 = min(x0 + 1, W - 1);
    int y1 = min(y0 + 1, W - 1);
    int r0 = y0 * W;
    int r1 = y1 * W;

    uint4 u00 = __ldg(tex + ((size_t)(r0 + x0) * 2 + h));
    uint4 u01 = __ldg(tex + ((size_t)(r0 + x1) * 2 + h));
    uint4 u10 = __ldg(tex + ((size_t)(r1 + x0) * 2 + h));
    uint4 u11 = __ldg(tex + ((size_t)(r1 + x1) * 2 + h));

    float v00[8], v01[8], v10[8], v11[8];
    up8(u00, v00); up8(u01, v01); up8(u10, v10); up8(u11, v11);

    float w00 = (1.0f - wx) * (1.0f - wy);
    float w01 = wx * (1.0f - wy);
    float w10 = (1.0f - wx) * wy;
    float w11 = wx * wy;

#pragma unroll
    for (int j = 0; j < 8; j++)
        acc[j] += w00 * v00[j] + w01 * v01[j] + w10 * v10[j] + w11 * v11[j];
}

// ---------------------------------------------------------------------------
// Gather: one thread per (pixel, feature-half). t = p*2 + h so each lane pair
// covers one pixel's 32B texel record with a single LDG.128 per corner.
// ---------------------------------------------------------------------------
__global__ void __launch_bounds__(256) gather_kernel(const float* __restrict__ grid,
                                                     float* __restrict__ out) {
    int t = blockIdx.x * blockDim.x + threadIdx.x;
    int p = t >> 1;              // pixel 0..2^20-1
    int h = t & 1;               // feature half 0..1

    float2 g = __ldg((const float2*)grid + p);   // lane pairs broadcast same 8B

    float acc[8];
#pragma unroll
    for (int j = 0; j < 8; j++) acc[j] = 0.0f;

    sample_level(g_p1, W1, g.x, g.y, h, acc);
    sample_level(g_p2, W2, g.x, g.y, h, acc);
    sample_level(g_p3, W3, g.x, g.y, h, acc);
    sample_level(g_p4, W4, g.x, g.y, h, acc);

    int b  = p >> 18;            // batch
    int hw = p & (HWO - 1);
    // out layout: (B, F, Ho, Wo); this thread owns features 8h..8h+7
    size_t base = ((size_t)(b * FEAT + h * 8) << 18) | (unsigned)hw;
#pragma unroll
    for (int j = 0; j < 8; j++)
        __stcs(out + base + (size_t)j * HWO, acc[j]);   // streaming: keep texels in L2
}

extern "C" void kernel_launch(void* const* d_in, const int* in_sizes, int n_in,
                              void* d_out, int out_size) {
    const float* x    = (const float*)d_in[0];   // (4, 512, 512, 2)
    const float* tex1 = (const float*)d_in[1];   // (16, 1024, 1024)
    const float* tex2 = (const float*)d_in[2];   // (16, 512, 512)
    const float* tex3 = (const float*)d_in[3];   // (16, 256, 256)
    const float* tex4 = (const float*)d_in[4];   // (16, 128, 128)
    float* out = (float*)d_out;                  // (4, 16, 512, 512)

    // Fused repack: all levels -> fp16 AoS records.
    const int total_texels = N1 + N2 + N3 + N4;  // 1,376,256
    repack_fused_kernel<<<(total_texels + 255) / 256, 256>>>(tex1, tex2, tex3, tex4);

    // Gather + blend + sum levels. One thread per (pixel, feature-half).
    gather_kernel<<<(2 * NPIX) / 256, 256>>>(x, out);
}

// round 6
// speedup vs baseline: 3.6316x; 1.1475x over previous
#include <cuda_runtime.h>
#include <cuda_fp16.h>

// Problem constants
#define GRID_HW 512
#define HWO     (GRID_HW * GRID_HW)          // 262144 = 2^18
#define NPIX    (4 * HWO)                    // 1048576 = 2^20
#define FEAT    16

// Level sizes (square textures)
#define W1 1024
#define W2 512
#define W3 256
#define W4 128
#define N1 (W1 * W1)
#define N2 (W2 * W2)
#define N3 (W3 * W3)
#define N4 (W4 * W4)

// Feature-interleaved fp16 packed textures: one texel = 16 halfs = 32B record
// stored as 2 x uint4 (features 0-7, 8-15). 42.5 MB total -> L2 resident.
__device__ __align__(16) static uint4 g_p1[N1 * 2];   // 32 MB
__device__ __align__(16) static uint4 g_p2[N2 * 2];   //  8 MB
__device__ __align__(16) static uint4 g_p3[N3 * 2];   //  2 MB
__device__ __align__(16) static uint4 g_p4[N4 * 2];   //  0.5 MB

// ---------------------------------------------------------------------------
// Fused repack: all 4 levels in one kernel. src (F, H, W) fp32 channel-major
// -> dst AoS fp16 records. Two consecutive texels per thread: float2 loads
// per feature (coalesced), 64B contiguous stores per thread.
// ---------------------------------------------------------------------------
__global__ void __launch_bounds__(256) repack_fused_kernel(
    const float* __restrict__ t1, const float* __restrict__ t2,
    const float* __restrict__ t3, const float* __restrict__ t4) {
    int idx = blockIdx.x * blockDim.x + threadIdx.x;   // texel pair index

    const float* src;
    uint4* dst;
    int pair, HW;
    const int H1 = N1 / 2, H2 = H1 + N2 / 2, H3 = H2 + N3 / 2, H4 = H3 + N4 / 2;
    if (idx < H1)      { src = t1; dst = g_p1; pair = idx;      HW = N1; }
    else if (idx < H2) { src = t2; dst = g_p2; pair = idx - H1; HW = N2; }
    else if (idx < H3) { src = t3; dst = g_p3; pair = idx - H2; HW = N3; }
    else if (idx < H4) { src = t4; dst = g_p4; pair = idx - H3; HW = N4; }
    else return;

    int lin = pair * 2;

    half2 r0[8], r1[8];
#pragma unroll
    for (int f = 0; f < 8; f++) {
        float2 a = __ldcs((const float2*)(src + (size_t)(2 * f)     * HW + lin));
        float2 b = __ldcs((const float2*)(src + (size_t)(2 * f + 1) * HW + lin));
        r0[f] = __floats2half2_rn(a.x, b.x);   // texel lin
        r1[f] = __floats2half2_rn(a.y, b.y);   // texel lin+1
    }
    uint4 o;
    o.x = *reinterpret_cast<unsigned*>(&r0[0]); o.y = *reinterpret_cast<unsigned*>(&r0[1]);
    o.z = *reinterpret_cast<unsigned*>(&r0[2]); o.w = *reinterpret_cast<unsigned*>(&r0[3]);
    dst[(size_t)lin * 2 + 0] = o;
    o.x = *reinterpret_cast<unsigned*>(&r0[4]); o.y = *reinterpret_cast<unsigned*>(&r0[5]);
    o.z = *reinterpret_cast<unsigned*>(&r0[6]); o.w = *reinterpret_cast<unsigned*>(&r0[7]);
    dst[(size_t)lin * 2 + 1] = o;
    o.x = *reinterpret_cast<unsigned*>(&r1[0]); o.y = *reinterpret_cast<unsigned*>(&r1[1]);
    o.z = *reinterpret_cast<unsigned*>(&r1[2]); o.w = *reinterpret_cast<unsigned*>(&r1[3]);
    dst[(size_t)lin * 2 + 2] = o;
    o.x = *reinterpret_cast<unsigned*>(&r1[4]); o.y = *reinterpret_cast<unsigned*>(&r1[5]);
    o.z = *reinterpret_cast<unsigned*>(&r1[6]); o.w = *reinterpret_cast<unsigned*>(&r1[7]);
    dst[(size_t)lin * 2 + 3] = o;
}

// Unpack 8 packed halfs (one uint4 = 16B) into 8 floats.
__device__ __forceinline__ void up8(uint4 u, float* v) {
    float2 f0 = __half22float2(*reinterpret_cast<half2*>(&u.x));
    float2 f1 = __half22float2(*reinterpret_cast<half2*>(&u.y));
    float2 f2 = __half22float2(*reinterpret_cast<half2*>(&u.z));
    float2 f3 = __half22float2(*reinterpret_cast<half2*>(&u.w));
    v[0] = f0.x; v[1] = f0.y; v[2] = f1.x; v[3] = f1.y;
    v[4] = f2.x; v[5] = f2.y; v[6] = f3.x; v[7] = f3.y;
}

// ---------------------------------------------------------------------------
// One level, one (feature-half, x-side) lane. The 4 lanes of a pixel cover
// the 64B span [x0*32, x0*32+64) per row -> the L1 coalescer merges each
// row-load into 1 wavefront when the span stays in a 128B line (75%).
// Lane accumulates its side's partial blend: wxs * (wy0*v_r0 + wy1*v_r1).
// ---------------------------------------------------------------------------
__device__ __forceinline__ void sample_level(const uint4* __restrict__ tex, int W,
                                             float gx, float gy, int h, int side,
                                             float* acc) {
    const float Wf = (float)W;
    float ix = ((gx + 1.0f) * Wf - 1.0f) * 0.5f;
    float iy = ((gy + 1.0f) * Wf - 1.0f) * 0.5f;
    ix = fminf(fmaxf(ix, 0.0f), Wf - 1.0f);
    iy = fminf(fmaxf(iy, 0.0f), Wf - 1.0f);
    float x0f = floorf(ix);
    float y0f = floorf(iy);
    float wx = ix - x0f;
    float wy = iy - y0f;
    int x0 = (int)x0f;
    int y0 = (int)y0f;

    int   xs  = side ? min(x0 + 1, W - 1) : x0;
    float wxs = side ? wx : (1.0f - wx);
    int   y1  = min(y0 + 1, W - 1);

    uint4 u0 = __ldg(tex + ((size_t)(y0 * W + xs) * 2 + h));   // row y0
    uint4 u1 = __ldg(tex + ((size_t)(y1 * W + xs) * 2 + h));   // row y1

    float v0[8], v1[8];
    up8(u0, v0); up8(u1, v1);

    float wy0 = (1.0f - wy) * wxs;
    float wy1 = wy * wxs;
#pragma unroll
    for (int j = 0; j < 8; j++)
        acc[j] += wy0 * v0[j] + wy1 * v1[j];
}

// ---------------------------------------------------------------------------
// Gather: one thread per (pixel, feature-half, x-side). t = p*4 + side*2 + h.
// After accumulating all levels, shfl.xor(2) folds the two x-sides together;
// side-0 lanes write the 8 output features.
// ---------------------------------------------------------------------------
__global__ void __launch_bounds__(256) gather_kernel(const float* __restrict__ grid,
                                                     float* __restrict__ out) {
    int t = blockIdx.x * blockDim.x + threadIdx.x;
    int p    = t >> 2;           // pixel 0..2^20-1
    int h    = t & 1;            // feature half
    int side = (t >> 1) & 1;     // x corner side

    float2 g = __ldg((const float2*)grid + p);

    float acc[8];
#pragma unroll
    for (int j = 0; j < 8; j++) acc[j] = 0.0f;

    sample_level(g_p1, W1, g.x, g.y, h, side, acc);
    sample_level(g_p2, W2, g.x, g.y, h, side, acc);
    sample_level(g_p3, W3, g.x, g.y, h, side, acc);
    sample_level(g_p4, W4, g.x, g.y, h, side, acc);

    // Fold x-sides: lane (p, side, h) <-> (p, side^1, h)
#pragma unroll
    for (int j = 0; j < 8; j++)
        acc[j] += __shfl_xor_sync(0xffffffffu, acc[j], 2);

    if (side == 0) {
        int b  = p >> 18;        // batch
        int hw = p & (HWO - 1);
        // out layout: (B, F, Ho, Wo); this lane owns features 8h..8h+7
        size_t base = ((size_t)(b * FEAT + h * 8) << 18) | (unsigned)hw;
#pragma unroll
        for (int j = 0; j < 8; j++)
            __stcs(out + base + (size_t)j * HWO, acc[j]);  // streaming stores
    }
}

extern "C" void kernel_launch(void* const* d_in, const int* in_sizes, int n_in,
                              void* d_out, int out_size) {
    const float* x    = (const float*)d_in[0];   // (4, 512, 512, 2)
    const float* tex1 = (const float*)d_in[1];   // (16, 1024, 1024)
    const float* tex2 = (const float*)d_in[2];   // (16, 512, 512)
    const float* tex3 = (const float*)d_in[3];   // (16, 256, 256)
    const float* tex4 = (const float*)d_in[4];   // (16, 128, 128)
    float* out = (float*)d_out;                  // (4, 16, 512, 512)

    // Fused repack: all levels -> fp16 AoS records. Two texels per thread.
    const int total_pairs = (N1 + N2 + N3 + N4) / 2;   // 688,128
    repack_fused_kernel<<<(total_pairs + 255) / 256, 256>>>(tex1, tex2, tex3, tex4);

    // Gather + blend + sum levels. One thread per (pixel, half, side).
    gather_kernel<<<(4 * NPIX) / 256, 256>>>(x, out);
}

// round 7
// speedup vs baseline: 3.7699x; 1.0381x over previous
#include <cuda_runtime.h>
#include <cuda_fp16.h>

// Problem constants
#define GRID_HW 512
#define HWO     (GRID_HW * GRID_HW)          // 262144 = 2^18
#define NPIX    (4 * HWO)                    // 1048576 = 2^20
#define FEAT    16

// Level sizes (square textures)
#define W1 1024
#define W2 512
#define W3 256
#define W4 128
#define N1 (W1 * W1)
#define N2 (W2 * W2)
#define N3 (W3 * W3)
#define N4 (W4 * W4)

// Feature-interleaved fp16 packed textures: one texel = 16 halfs = 32B record
// stored as 2 x uint4 (features 0-7, 8-15). 42.5 MB total -> L2 resident.
__device__ __align__(16) static uint4 g_p1[N1 * 2];   // 32 MB
__device__ __align__(16) static uint4 g_p2[N2 * 2];   //  8 MB
__device__ __align__(16) static uint4 g_p3[N3 * 2];   //  2 MB
__device__ __align__(16) static uint4 g_p4[N4 * 2];   //  0.5 MB

// ---------------------------------------------------------------------------
// Fused repack: all 4 levels in one kernel. src (F, H, W) fp32 channel-major
// -> dst AoS fp16 records. Two consecutive texels per thread (float2 loads,
// 64B contiguous stores). DRAM-bound at ~128 MB traffic.
// ---------------------------------------------------------------------------
__global__ void __launch_bounds__(256) repack_fused_kernel(
    const float* __restrict__ t1, const float* __restrict__ t2,
    const float* __restrict__ t3, const float* __restrict__ t4) {
    int idx = blockIdx.x * blockDim.x + threadIdx.x;   // texel pair index

    const float* src;
    uint4* dst;
    int pair, HW;
    const int H1 = N1 / 2, H2 = H1 + N2 / 2, H3 = H2 + N3 / 2, H4 = H3 + N4 / 2;
    if (idx < H1)      { src = t1; dst = g_p1; pair = idx;      HW = N1; }
    else if (idx < H2) { src = t2; dst = g_p2; pair = idx - H1; HW = N2; }
    else if (idx < H3) { src = t3; dst = g_p3; pair = idx - H2; HW = N3; }
    else if (idx < H4) { src = t4; dst = g_p4; pair = idx - H3; HW = N4; }
    else return;

    int lin = pair * 2;

    half2 r0[8], r1[8];
#pragma unroll
    for (int f = 0; f < 8; f++) {
        float2 a = __ldcs((const float2*)(src + (size_t)(2 * f)     * HW + lin));
        float2 b = __ldcs((const float2*)(src + (size_t)(2 * f + 1) * HW + lin));
        r0[f] = __floats2half2_rn(a.x, b.x);   // texel lin
        r1[f] = __floats2half2_rn(a.y, b.y);   // texel lin+1
    }
    uint4 o;
    o.x = *reinterpret_cast<unsigned*>(&r0[0]); o.y = *reinterpret_cast<unsigned*>(&r0[1]);
    o.z = *reinterpret_cast<unsigned*>(&r0[2]); o.w = *reinterpret_cast<unsigned*>(&r0[3]);
    dst[(size_t)lin * 2 + 0] = o;
    o.x = *reinterpret_cast<unsigned*>(&r0[4]); o.y = *reinterpret_cast<unsigned*>(&r0[5]);
    o.z = *reinterpret_cast<unsigned*>(&r0[6]); o.w = *reinterpret_cast<unsigned*>(&r0[7]);
    dst[(size_t)lin * 2 + 1] = o;
    o.x = *reinterpret_cast<unsigned*>(&r1[0]); o.y = *reinterpret_cast<unsigned*>(&r1[1]);
    o.z = *reinterpret_cast<unsigned*>(&r1[2]); o.w = *reinterpret_cast<unsigned*>(&r1[3]);
    dst[(size_t)lin * 2 + 2] = o;
    o.x = *reinterpret_cast<unsigned*>(&r1[4]); o.y = *reinterpret_cast<unsigned*>(&r1[5]);
    o.z = *reinterpret_cast<unsigned*>(&r1[6]); o.w = *reinterpret_cast<unsigned*>(&r1[7]);
    dst[(size_t)lin * 2 + 3] = o;
}

// ---------------------------------------------------------------------------
// Gather: one thread per (pixel, feature-half, x-side). t = p*4 + side*2 + h.
// Phase A: coords/weights/addresses for all 4 levels (derived-coordinate
// chain), all 8 LDG.128 issued back-to-back (MLP=8).
// Phase B: per level fold rows y0/y1 in half2 (4 HMUL2 + 4 HFMA2), convert,
// fp32-accumulate scaled by this lane's x-side weight.
// Epilogue: shfl.xor(2) folds the two x-sides; side-0 lanes store.
// ---------------------------------------------------------------------------
__global__ void __launch_bounds__(256) gather_kernel(const float* __restrict__ grid,
                                                     float* __restrict__ out) {
    int t = blockIdx.x * blockDim.x + threadIdx.x;
    int p    = t >> 2;           // pixel 0..2^20-1
    int h    = t & 1;            // feature half
    int side = (t >> 1) & 1;     // x corner side

    float2 g = __ldg((const float2*)grid + p);

    const uint4* __restrict__ texs[4] = { g_p1, g_p2, g_p3, g_p4 };
    const int Ws[4] = { W1, W2, W3, W4 };

    // Unclamped level-1 coords; per-level derived by ix' = 0.5*ix - 0.25.
    float ix = ((g.x + 1.0f) * (float)W1 - 1.0f) * 0.5f;
    float iy = ((g.y + 1.0f) * (float)W1 - 1.0f) * 0.5f;

    uint4 u0[4], u1[4];
    half2 w0h[4], w1h[4];
    float wxs[4];

#pragma unroll
    for (int L = 0; L < 4; L++) {
        const int   W  = Ws[L];
        const float Wf = (float)W;
        float cx = fminf(fmaxf(ix, 0.0f), Wf - 1.0f);
        float cy = fminf(fmaxf(iy, 0.0f), Wf - 1.0f);
        float x0f = floorf(cx);
        float y0f = floorf(cy);
        float wx = cx - x0f;
        float wy = cy - y0f;
        int x0 = (int)x0f;
        int y0 = (int)y0f;
        int xs = side ? min(x0 + 1, W - 1) : x0;
        int y1 = min(y0 + 1, W - 1);

        wxs[L] = side ? wx : (1.0f - wx);
        w0h[L] = __float2half2_rn(1.0f - wy);
        w1h[L] = __float2half2_rn(wy);

        const uint4* base = texs[L];
        u0[L] = __ldg(base + ((y0 * W + xs) * 2 + h));
        u1[L] = __ldg(base + ((y1 * W + xs) * 2 + h));

        ix = ix * 0.5f - 0.25f;
        iy = iy * 0.5f - 0.25f;
    }

    float acc[8];
#pragma unroll
    for (int j = 0; j < 8; j++) acc[j] = 0.0f;

#pragma unroll
    for (int L = 0; L < 4; L++) {
        const half2* v0 = reinterpret_cast<const half2*>(&u0[L]);
        const half2* v1 = reinterpret_cast<const half2*>(&u1[L]);
        float ws = wxs[L];
#pragma unroll
        for (int k = 0; k < 4; k++) {
            half2 tk = __hfma2(v1[k], w1h[L], __hmul2(v0[k], w0h[L]));
            float2 tf = __half22float2(tk);
            acc[2 * k]     = fmaf(tf.x, ws, acc[2 * k]);
            acc[2 * k + 1] = fmaf(tf.y, ws, acc[2 * k + 1]);
        }
    }

    // Fold x-sides: lane (p, side, h) <-> (p, side^1, h)
#pragma unroll
    for (int j = 0; j < 8; j++)
        acc[j] += __shfl_xor_sync(0xffffffffu, acc[j], 2);

    if (side == 0) {
        int b  = p >> 18;        // batch
        int hw = p & (HWO - 1);
        // out layout: (B, F, Ho, Wo); this lane owns features 8h..8h+7
        size_t base = ((size_t)(b * FEAT + h * 8) << 18) | (unsigned)hw;
#pragma unroll
        for (int j = 0; j < 8; j++)
            __stcs(out + base + (size_t)j * HWO, acc[j]);  // streaming stores
    }
}

extern "C" void kernel_launch(void* const* d_in, const int* in_sizes, int n_in,
                              void* d_out, int out_size) {
    const float* x    = (const float*)d_in[0];   // (4, 512, 512, 2)
    const float* tex1 = (const float*)d_in[1];   // (16, 1024, 1024)
    const float* tex2 = (const float*)d_in[2];   // (16, 512, 512)
    const float* tex3 = (const float*)d_in[3];   // (16, 256, 256)
    const float* tex4 = (const float*)d_in[4];   // (16, 128, 128)
    float* out = (float*)d_out;                  // (4, 16, 512, 512)

    // Fused repack: all levels -> fp16 AoS records. Two texels per thread.
    const int total_pairs = (N1 + N2 + N3 + N4) / 2;   // 688,128
    repack_fused_kernel<<<(total_pairs + 255) / 256, 256>>>(tex1, tex2, tex3, tex4);

    // Gather + blend + sum levels. One thread per (pixel, half, side).
    gather_kernel<<<(4 * NPIX) / 256, 256>>>(x, out);
}